// round 3
// baseline (speedup 1.0000x reference)
#include <cuda_runtime.h>
#include <cuda_bf16.h>
#include <math.h>

#define NN 50000
#define EE 800000
#define ET (EE + NN)       // edges + self loops = 850000
#define DD 128
#define NG 64
#define NEG_SLOPE 0.2f

// ---------------- static device scratch (no allocations allowed) ----------------
__device__ float g_hA[(size_t)NN * DD];   // gemm output (per layer)
__device__ float g_hB[(size_t)NN * DD];   // layer-1 aggregate output
__device__ float g_as[NN];
__device__ float g_ad[NN];
__device__ int   g_deg[NN];
__device__ int   g_rowptr[NN + 1];
__device__ int   g_cursor[NN];
__device__ int   g_src[ET];               // CSR adjacency (src per slot)
__device__ int   g_gmin[NG];
__device__ int   g_gmax[NG];

// ---------------- init ----------------
__global__ void zero_kernel() {
    int i = blockIdx.x * blockDim.x + threadIdx.x;
    if (i < NN) g_deg[i] = 0;
    if (i < NG) { g_gmin[i] = NN; g_gmax[i] = -1; }
}

// ---------------- CSR build (edge_index delivered as int32) ----------------
__global__ void hist_kernel(const int* __restrict__ ei) {
    int e = blockIdx.x * blockDim.x + threadIdx.x;
    if (e >= ET) return;
    int dst = (e < EE) ? ei[EE + e] : (e - EE);
    atomicAdd(&g_deg[dst], 1);
}

// exclusive scan of degrees (single block, 1024 threads)
__global__ void scan_kernel() {
    __shared__ int sh[1024];
    __shared__ int carry_sh;
    int t = threadIdx.x;
    if (t == 0) carry_sh = 0;
    __syncthreads();
    for (int base = 0; base < NN; base += 1024) {
        int v = (base + t < NN) ? g_deg[base + t] : 0;
        int orig = v;
        sh[t] = v;
        __syncthreads();
        for (int off = 1; off < 1024; off <<= 1) {
            int add = (t >= off) ? sh[t - off] : 0;
            __syncthreads();
            sh[t] += add;
            __syncthreads();
        }
        int incl = sh[t];
        int ex = carry_sh + incl - orig;
        if (base + t < NN) { g_rowptr[base + t] = ex; g_cursor[base + t] = ex; }
        __syncthreads();
        if (t == 1023) carry_sh += sh[1023];
        __syncthreads();
    }
    if (t == 0) g_rowptr[NN] = carry_sh;
}

__global__ void scatter_kernel(const int* __restrict__ ei) {
    int e = blockIdx.x * blockDim.x + threadIdx.x;
    if (e >= ET) return;
    int src, dst;
    if (e < EE) { src = ei[e]; dst = ei[EE + e]; }
    else        { src = e - EE; dst = e - EE; }
    int pos = atomicAdd(&g_cursor[dst], 1);
    g_src[pos] = src;
}

__global__ void bounds_kernel(const int* __restrict__ batch) {
    int i = blockIdx.x * blockDim.x + threadIdx.x;
    if (i >= NN) return;
    int g = batch[i];
    atomicMin(&g_gmin[g], i);
    atomicMax(&g_gmax[g], i);
}

// ---------------- GEMM (h = X@W) + fused alpha projections ----------------
// block: 256 threads; tile: 64 rows x 128 cols; thread: 8 rows x 4 cols
__global__ void gemm_alpha_kernel(const float* __restrict__ X,
                                  const float* __restrict__ W,
                                  const float* __restrict__ a_s,
                                  const float* __restrict__ a_d,
                                  float* __restrict__ H) {
    __shared__ float xs[64 * 128];
    int t  = threadIdx.x;
    int tx = t & 31;        // col group: cols 4*tx .. 4*tx+3
    int ty = t >> 5;        // warp id: rows ty*8 .. ty*8+7
    int rowbase = blockIdx.x * 64;

    for (int idx = t; idx < 64 * 128; idx += 256) {
        int r = idx >> 7;
        xs[idx] = (rowbase + r < NN) ? X[(size_t)rowbase * 128 + idx] : 0.f;
    }
    __syncthreads();

    float acc[8][4];
    #pragma unroll
    for (int j = 0; j < 8; j++)
        #pragma unroll
        for (int c = 0; c < 4; c++) acc[j][c] = 0.f;

    const float4* W4 = (const float4*)W;
    #pragma unroll 4
    for (int k = 0; k < 128; k++) {
        float4 w = W4[k * 32 + tx];
        #pragma unroll
        for (int j = 0; j < 8; j++) {
            float xv = xs[(ty * 8 + j) * 128 + k];
            acc[j][0] += xv * w.x;
            acc[j][1] += xv * w.y;
            acc[j][2] += xv * w.z;
            acc[j][3] += xv * w.w;
        }
    }

    float4 asv = ((const float4*)a_s)[tx];
    float4 adv = ((const float4*)a_d)[tx];
    #pragma unroll
    for (int j = 0; j < 8; j++) {
        int row = rowbase + ty * 8 + j;
        float ps = acc[j][0]*asv.x + acc[j][1]*asv.y + acc[j][2]*asv.z + acc[j][3]*asv.w;
        float pd = acc[j][0]*adv.x + acc[j][1]*adv.y + acc[j][2]*adv.z + acc[j][3]*adv.w;
        #pragma unroll
        for (int off = 16; off > 0; off >>= 1) {
            ps += __shfl_down_sync(0xFFFFFFFFu, ps, off);
            pd += __shfl_down_sync(0xFFFFFFFFu, pd, off);
        }
        if (row < NN) {
            ((float4*)H)[(size_t)row * 32 + tx] =
                make_float4(acc[j][0], acc[j][1], acc[j][2], acc[j][3]);
            if (tx == 0) { g_as[row] = ps; g_ad[row] = pd; }
        }
    }
}

// ---------------- edge softmax + aggregate: warp per dst node ----------------
__global__ void aggregate_kernel(const float* __restrict__ H,
                                 const float* __restrict__ bias,
                                 float* __restrict__ OUT) {
    int warp = (blockIdx.x * blockDim.x + threadIdx.x) >> 5;
    int lane = threadIdx.x & 31;
    if (warp >= NN) return;
    int dst = warp;
    int start = g_rowptr[dst];
    int end   = g_rowptr[dst + 1];
    float add = g_ad[dst];

    // pass 1: max
    float m = -1e30f;
    for (int i = start + lane; i < end; i += 32) {
        int s = g_src[i];
        float e = g_as[s] + add;
        e = (e > 0.f) ? e : NEG_SLOPE * e;
        m = fmaxf(m, e);
    }
    #pragma unroll
    for (int off = 16; off > 0; off >>= 1)
        m = fmaxf(m, __shfl_xor_sync(0xFFFFFFFFu, m, off));

    // pass 2: sum of exp
    float ssum = 0.f;
    for (int i = start + lane; i < end; i += 32) {
        int s = g_src[i];
        float e = g_as[s] + add;
        e = (e > 0.f) ? e : NEG_SLOPE * e;
        ssum += __expf(e - m);
    }
    #pragma unroll
    for (int off = 16; off > 0; off >>= 1)
        ssum += __shfl_xor_sync(0xFFFFFFFFu, ssum, off);
    float inv = 1.f / (ssum + 1e-16f);

    // pass 3: weighted gather of h[src]
    float4 acc = make_float4(0.f, 0.f, 0.f, 0.f);
    const float4* H4 = (const float4*)H;
    for (int i = start; i < end; i++) {
        int s = g_src[i];
        float e = g_as[s] + add;
        e = (e > 0.f) ? e : NEG_SLOPE * e;
        float coef = __expf(e - m) * inv;
        float4 hv = H4[(size_t)s * 32 + lane];
        acc.x += hv.x * coef;
        acc.y += hv.y * coef;
        acc.z += hv.z * coef;
        acc.w += hv.w * coef;
    }
    float4 b = ((const float4*)bias)[lane];
    acc.x += b.x; acc.y += b.y; acc.z += b.z; acc.w += b.w;
    ((float4*)OUT)[(size_t)dst * 32 + lane] = acc;
}

// ---------------- global mean pool ----------------
__global__ void pool_kernel(const float* __restrict__ FE, float* __restrict__ POOL) {
    __shared__ float sh[256];
    int g = blockIdx.x;
    int d = threadIdx.x & 127;
    int half = threadIdx.x >> 7;
    int lo = g_gmin[g], hi = g_gmax[g];
    float sum = 0.f;
    for (int n = lo + half; n <= hi; n += 2)
        sum += FE[(size_t)n * 128 + d];
    sh[threadIdx.x] = sum;
    __syncthreads();
    if (half == 0) {
        if (hi >= lo) {
            float tot = sh[d] + sh[d + 128];
            float cnt = (float)(hi - lo + 1);
            POOL[g * 128 + d] = tot / cnt;
        } else {
            POOL[g * 128 + d] = 0.f;
        }
    }
}

// ---------------- launch ----------------
extern "C" void kernel_launch(void* const* d_in, const int* in_sizes, int n_in,
                              void* d_out, int out_size) {
    const float* x     = (const float*)d_in[0];
    const int*   ei    = (const int*)d_in[1];
    const int*   batch = (const int*)d_in[2];
    const float* W1    = (const float*)d_in[3];
    const float* as1   = (const float*)d_in[4];
    const float* ad1   = (const float*)d_in[5];
    const float* b1    = (const float*)d_in[6];
    const float* W2    = (const float*)d_in[7];
    const float* as2   = (const float*)d_in[8];
    const float* ad2   = (const float*)d_in[9];
    const float* b2    = (const float*)d_in[10];
    float* out = (float*)d_out;

    float* hA;  cudaGetSymbolAddress((void**)&hA, g_hA);
    float* hB;  cudaGetSymbolAddress((void**)&hB, g_hB);

    // CSR + graph bounds (identical for both layers)
    zero_kernel<<<(NN + 255) / 256, 256>>>();
    hist_kernel<<<(ET + 255) / 256, 256>>>(ei);
    scan_kernel<<<1, 1024>>>();
    scatter_kernel<<<(ET + 255) / 256, 256>>>(ei);
    bounds_kernel<<<(NN + 255) / 256, 256>>>(batch);

    int gemm_grid = (NN + 63) / 64;
    int agg_grid  = (NN + 7) / 8;   // 8 warps (nodes) per 256-thread block

    // layer 1
    gemm_alpha_kernel<<<gemm_grid, 256>>>(x, W1, as1, ad1, hA);
    aggregate_kernel<<<agg_grid, 256>>>(hA, b1, hB);

    // layer 2 (feats written straight into d_out)
    gemm_alpha_kernel<<<gemm_grid, 256>>>(hB, W2, as2, ad2, hA);
    aggregate_kernel<<<agg_grid, 256>>>(hA, b2, out);

    // mean pool into d_out tail
    pool_kernel<<<NG, 256>>>(out, out + (size_t)NN * DD);
}

// round 5
// speedup vs baseline: 1.4994x; 1.4994x over previous
#include <cuda_runtime.h>
#include <cuda_bf16.h>
#include <math.h>

#define NN 50000
#define EE 800000
#define ET (EE + NN)       // edges + self loops = 850000
#define DD 128
#define NG 64
#define NEG_SLOPE 0.2f
#define SCAN_BLK 1024
#define NSCAN ((NN + SCAN_BLK - 1) / SCAN_BLK)   // 49

// ---------------- static device scratch (no allocations allowed) ----------------
__device__ float g_hA[(size_t)NN * DD];   // gemm output (per layer)
__device__ float g_hB[(size_t)NN * DD];   // layer-1 aggregate output
__device__ float g_as[NN];
__device__ float g_ad[NN];
__device__ int   g_deg[NN];
__device__ int   g_rowptr[NN + 1];
__device__ int   g_cursor[NN];            // doubles as local-scan tmp
__device__ int   g_src[ET];               // CSR adjacency (src per slot)
__device__ int   g_bsum[NSCAN];
__device__ int   g_boff[NSCAN];
__device__ int   g_gmin[NG];
__device__ int   g_gmax[NG];
__device__ float g_pool[NG * DD];

// ---------------- init ----------------
__global__ void zero_kernel() {
    int i = blockIdx.x * blockDim.x + threadIdx.x;
    if (i < NN) g_deg[i] = 0;
    if (i < NG) { g_gmin[i] = NN; g_gmax[i] = -1; }
    if (i < NG * DD) g_pool[i] = 0.f;
}

// ---------------- CSR build (edge_index delivered as int32) ----------------
__global__ void hist_kernel(const int* __restrict__ ei) {
    int e = blockIdx.x * blockDim.x + threadIdx.x;
    if (e >= ET) return;
    int dst = (e < EE) ? ei[EE + e] : (e - EE);
    atomicAdd(&g_deg[dst], 1);
}

// ---- hierarchical exclusive scan of degrees ----
__global__ void scan1_kernel() {          // grid NSCAN, block 1024
    __shared__ int wsum[32];
    int b = blockIdx.x, t = threadIdx.x;
    int i = b * SCAN_BLK + t;
    int lane = t & 31, wid = t >> 5;
    int v = (i < NN) ? g_deg[i] : 0;
    int x = v;
    #pragma unroll
    for (int off = 1; off < 32; off <<= 1) {
        int y = __shfl_up_sync(0xFFFFFFFFu, x, off);
        if (lane >= off) x += y;
    }
    if (lane == 31) wsum[wid] = x;
    __syncthreads();
    if (wid == 0) {
        int s = wsum[lane];
        #pragma unroll
        for (int off = 1; off < 32; off <<= 1) {
            int y = __shfl_up_sync(0xFFFFFFFFu, s, off);
            if (lane >= off) s += y;
        }
        wsum[lane] = s;
    }
    __syncthreads();
    int excl = x - v + (wid > 0 ? wsum[wid - 1] : 0);
    if (i < NN) g_cursor[i] = excl;       // block-local exclusive scan
    if (t == 0) g_bsum[b] = wsum[31];     // block total
}

__global__ void scan2_kernel() {          // tiny: serial scan of 49 block sums
    if (threadIdx.x == 0) {
        int run = 0;
        for (int b = 0; b < NSCAN; b++) { g_boff[b] = run; run += g_bsum[b]; }
        g_rowptr[NN] = run;
    }
}

__global__ void scan3_kernel() {          // add block offsets, write rowptr+cursor
    int i = blockIdx.x * blockDim.x + threadIdx.x;
    if (i >= NN) return;
    int r = g_cursor[i] + g_boff[i >> 10];
    g_rowptr[i] = r;
    g_cursor[i] = r;
}

__global__ void scatter_kernel(const int* __restrict__ ei) {
    int e = blockIdx.x * blockDim.x + threadIdx.x;
    if (e >= ET) return;
    int src, dst;
    if (e < EE) { src = ei[e]; dst = ei[EE + e]; }
    else        { src = e - EE; dst = e - EE; }
    int pos = atomicAdd(&g_cursor[dst], 1);
    g_src[pos] = src;
}

__global__ void bounds_kernel(const int* __restrict__ batch) {
    int i = blockIdx.x * blockDim.x + threadIdx.x;
    if (i >= NN) return;
    int g = batch[i];
    atomicMin(&g_gmin[g], i);
    atomicMax(&g_gmax[g], i);
}

// ---------------- GEMM (h = X@W) + fused alpha projections ----------------
// block: 256 threads; tile: 64 rows x 128 cols; thread: 8 rows x 4 cols
__global__ void gemm_alpha_kernel(const float* __restrict__ X,
                                  const float* __restrict__ W,
                                  const float* __restrict__ a_s,
                                  const float* __restrict__ a_d,
                                  float* __restrict__ H) {
    __shared__ float xs[64 * 128];
    int t  = threadIdx.x;
    int tx = t & 31;        // col group: cols 4*tx .. 4*tx+3
    int ty = t >> 5;        // warp id: rows ty*8 .. ty*8+7
    int rowbase = blockIdx.x * 64;

    for (int idx = t; idx < 64 * 128 / 4; idx += 256) {
        int r = idx >> 5;
        ((float4*)xs)[idx] = (rowbase + r < NN)
            ? ((const float4*)X)[(size_t)rowbase * 32 + idx]
            : make_float4(0.f, 0.f, 0.f, 0.f);
    }
    __syncthreads();

    float acc[8][4];
    #pragma unroll
    for (int j = 0; j < 8; j++)
        #pragma unroll
        for (int c = 0; c < 4; c++) acc[j][c] = 0.f;

    const float4* W4 = (const float4*)W;
    const float4* xs4 = (const float4*)xs;
    #pragma unroll 8
    for (int k4 = 0; k4 < 32; k4++) {
        float4 w0 = W4[(4 * k4 + 0) * 32 + tx];
        float4 w1 = W4[(4 * k4 + 1) * 32 + tx];
        float4 w2 = W4[(4 * k4 + 2) * 32 + tx];
        float4 w3 = W4[(4 * k4 + 3) * 32 + tx];
        #pragma unroll
        for (int j = 0; j < 8; j++) {
            float4 xv = xs4[(ty * 8 + j) * 32 + k4];
            acc[j][0] += xv.x * w0.x + xv.y * w1.x + xv.z * w2.x + xv.w * w3.x;
            acc[j][1] += xv.x * w0.y + xv.y * w1.y + xv.z * w2.y + xv.w * w3.y;
            acc[j][2] += xv.x * w0.z + xv.y * w1.z + xv.z * w2.z + xv.w * w3.z;
            acc[j][3] += xv.x * w0.w + xv.y * w1.w + xv.z * w2.w + xv.w * w3.w;
        }
    }

    float4 asv = ((const float4*)a_s)[tx];
    float4 adv = ((const float4*)a_d)[tx];
    #pragma unroll
    for (int j = 0; j < 8; j++) {
        int row = rowbase + ty * 8 + j;
        float ps = acc[j][0]*asv.x + acc[j][1]*asv.y + acc[j][2]*asv.z + acc[j][3]*asv.w;
        float pd = acc[j][0]*adv.x + acc[j][1]*adv.y + acc[j][2]*adv.z + acc[j][3]*adv.w;
        #pragma unroll
        for (int off = 16; off > 0; off >>= 1) {
            ps += __shfl_down_sync(0xFFFFFFFFu, ps, off);
            pd += __shfl_down_sync(0xFFFFFFFFu, pd, off);
        }
        if (row < NN) {
            ((float4*)H)[(size_t)row * 32 + tx] =
                make_float4(acc[j][0], acc[j][1], acc[j][2], acc[j][3]);
            if (tx == 0) { g_as[row] = ps; g_ad[row] = pd; }
        }
    }
}

// ---------------- single-pass online-softmax aggregate: warp per dst ----------------
__global__ void aggregate_kernel(const float* __restrict__ H,
                                 const float* __restrict__ bias,
                                 float* __restrict__ OUT) {
    int warp = (blockIdx.x * blockDim.x + threadIdx.x) >> 5;
    int lane = threadIdx.x & 31;
    if (warp >= NN) return;
    int dst = warp;
    int start = g_rowptr[dst];
    int end   = g_rowptr[dst + 1];
    float add = g_ad[dst];

    float m = -1e30f;
    float ssum = 0.f;
    float4 acc = make_float4(0.f, 0.f, 0.f, 0.f);
    const float4* H4 = (const float4*)H;

    for (int i = start; i < end; i++) {
        int s = g_src[i];                     // uniform across warp
        float e = g_as[s] + add;              // broadcast load
        e = (e > 0.f) ? e : NEG_SLOPE * e;
        float newm = fmaxf(m, e);
        float scale = __expf(m - newm);       // 1 when m unchanged; 0 on first iter
        float w = __expf(e - newm);
        ssum = ssum * scale + w;
        float4 hv = H4[(size_t)s * 32 + lane];
        acc.x = acc.x * scale + w * hv.x;
        acc.y = acc.y * scale + w * hv.y;
        acc.z = acc.z * scale + w * hv.z;
        acc.w = acc.w * scale + w * hv.w;
        m = newm;
    }
    float inv = 1.f / (ssum + 1e-16f);
    float4 b = ((const float4*)bias)[lane];
    acc.x = acc.x * inv + b.x;
    acc.y = acc.y * inv + b.y;
    acc.z = acc.z * inv + b.z;
    acc.w = acc.w * inv + b.w;
    ((float4*)OUT)[(size_t)dst * 32 + lane] = acc;
}

// ---------------- global mean pool (parallel partial sums + normalize) ----------------
__global__ void pool_part_kernel(const float* __restrict__ FE) {
    // grid (NG, 8); block 128 threads = one feature each
    int g = blockIdx.x;
    int part = blockIdx.y;
    int d = threadIdx.x;
    int lo = g_gmin[g], hi = g_gmax[g];
    if (hi < lo) return;
    int cnt = hi - lo + 1;
    int chunk = (cnt + 7) / 8;
    int s = lo + part * chunk;
    int e = min(s + chunk, hi + 1);
    if (s >= e) return;
    float sum = 0.f;
    for (int n = s; n < e; n++)
        sum += FE[(size_t)n * 128 + d];
    atomicAdd(&g_pool[g * 128 + d], sum);
}

__global__ void pool_final_kernel(float* __restrict__ POOL) {
    int i = blockIdx.x * blockDim.x + threadIdx.x;
    if (i >= NG * DD) return;
    int g = i >> 7;
    int lo = g_gmin[g], hi = g_gmax[g];
    float cnt = (hi >= lo) ? (float)(hi - lo + 1) : 1.f;
    POOL[i] = (hi >= lo) ? g_pool[i] / cnt : 0.f;
}

// ---------------- launch ----------------
extern "C" void kernel_launch(void* const* d_in, const int* in_sizes, int n_in,
                              void* d_out, int out_size) {
    const float* x     = (const float*)d_in[0];
    const int*   ei    = (const int*)d_in[1];
    const int*   batch = (const int*)d_in[2];
    const float* W1    = (const float*)d_in[3];
    const float* as1   = (const float*)d_in[4];
    const float* ad1   = (const float*)d_in[5];
    const float* b1    = (const float*)d_in[6];
    const float* W2    = (const float*)d_in[7];
    const float* as2   = (const float*)d_in[8];
    const float* ad2   = (const float*)d_in[9];
    const float* b2    = (const float*)d_in[10];
    float* out = (float*)d_out;

    float* hA;  cudaGetSymbolAddress((void**)&hA, g_hA);
    float* hB;  cudaGetSymbolAddress((void**)&hB, g_hB);

    // CSR + graph bounds (identical for both layers)
    zero_kernel<<<(NN + 255) / 256, 256>>>();
    hist_kernel<<<(ET + 255) / 256, 256>>>(ei);
    scan1_kernel<<<NSCAN, SCAN_BLK>>>();
    scan2_kernel<<<1, 32>>>();
    scan3_kernel<<<(NN + 255) / 256, 256>>>();
    scatter_kernel<<<(ET + 255) / 256, 256>>>(ei);
    bounds_kernel<<<(NN + 255) / 256, 256>>>(batch);

    int gemm_grid = (NN + 63) / 64;
    int agg_grid  = (NN + 7) / 8;   // 8 warps (nodes) per 256-thread block

    // layer 1
    gemm_alpha_kernel<<<gemm_grid, 256>>>(x, W1, as1, ad1, hA);
    aggregate_kernel<<<agg_grid, 256>>>(hA, b1, hB);

    // layer 2 (feats written straight into d_out)
    gemm_alpha_kernel<<<gemm_grid, 256>>>(hB, W2, as2, ad2, hA);
    aggregate_kernel<<<agg_grid, 256>>>(hA, b2, out);

    // mean pool into d_out tail
    dim3 pgrid(NG, 8);
    pool_part_kernel<<<pgrid, 128>>>(out);
    pool_final_kernel<<<(NG * DD + 255) / 256, 256>>>(out + (size_t)NN * DD);
}